// round 12
// baseline (speedup 1.0000x reference)
#include <cuda_runtime.h>

// QConv2d: new_rho[b] = V * rho[b] * V^T,  V = kron(uc[:,2:4], ux, uy) (256x128).
// Channel insertion is a pure +128 index shift. Factorization:
//   M2 = (I2 (x) ux (x) uy) rho (I2 (x) ux (x) uy)^T   -- in-place, 68 KB smem
//   out block (g,g') = sum_{f,f'} c[g,f] c[g',f'] * M2 block (f,f')
// All arithmetic in packed f32x2 (Blackwell FFMA2 via PTX fma.rn.f32x2).
// One CTA per batch, 512 threads, 2 CTAs/SM, single wave.

#define SSTR 132   // row stride (floats): float2/float4 accesses conflict-free

typedef unsigned long long u64;

static constexpr int TAB_F      = 128 * SSTR;              // float offset of tables
static constexpr int SMEM_BYTES = TAB_F * 4 + 168 * 8;     // 68,928 B

__device__ __forceinline__ u64 ffma2(u64 a, u64 b, u64 c) {
    u64 d; asm("fma.rn.f32x2 %0, %1, %2, %3;" : "=l"(d) : "l"(a), "l"(b), "l"(c)); return d;
}
__device__ __forceinline__ u64 fmul2(u64 a, u64 b) {
    u64 d; asm("mul.rn.f32x2 %0, %1, %2;" : "=l"(d) : "l"(a), "l"(b)); return d;
}
__device__ __forceinline__ u64 bc2(float s) {
    u64 d; asm("mov.b64 %0, {%1, %1};" : "=l"(d) : "f"(s)); return d;
}
__device__ __forceinline__ u64 pk2(float lo, float hi) {
    u64 d; asm("mov.b64 %0, {%1, %2};" : "=l"(d) : "f"(lo), "f"(hi)); return d;
}

__global__ void __launch_bounds__(512, 2)
qconv_kernel(const float* __restrict__ rho_g,
             const float* __restrict__ ux_g,
             const float* __restrict__ uy_g,
             const float* __restrict__ uc_g,
             float* __restrict__ out_g)
{
    extern __shared__ float sm[];
    float* __restrict__ Ssh = sm;                             // [128][SSTR]
    u64*   __restrict__ TB  = reinterpret_cast<u64*>(sm + TAB_F);
    u64*   __restrict__ UyB = TB;        // [64]  (uy[l][j], uy[l][j])      at l*8+j
    u64*   __restrict__ UxB = TB + 64;   // [64]  (ux[k][i], ux[k][i])      at k*8+i
    u64*   __restrict__ UyT = TB + 128;  // [32]  (uy[2l2][j], uy[2l2+1][j]) at j*4+l2
    u64*   __restrict__ UcB = TB + 160;  // [8]   (c[g][f], c[g][f])        at g*2+f

    const int tid = threadIdx.x;
    const int b   = blockIdx.x;

    if (tid < 64) {
        UyB[tid] = bc2(uy_g[tid]);
        UxB[tid] = bc2(ux_g[tid]);
    } else if (tid < 96) {
        int t = tid - 64, j = t >> 2, l2 = t & 3;
        UyT[t] = pk2(uy_g[(2 * l2) * 8 + j], uy_g[(2 * l2 + 1) * 8 + j]);
    } else if (tid < 104) {
        int t = tid - 96;
        UcB[t] = bc2(uc_g[(t >> 1) * 4 + 2 + (t & 1)]);
    }

    // Load rho[b] (128x128 fp32), float4 coalesced.
    {
        const float4* __restrict__ src =
            reinterpret_cast<const float4*>(rho_g) + (size_t)b * 4096;
        #pragma unroll
        for (int it = 0; it < 8; it++) {
            int idx = tid + it * 512;
            int row = idx >> 5;
            int c4  = idx & 31;
            *reinterpret_cast<float4*>(Ssh + row * SSTR + c4 * 4) = src[idx];
        }
    }
    __syncthreads();

    // ---------- Stage 1: left (ux (x) uy) per COLUMN-PAIR, in place, f32x2 ----------
    {
        const int cp  = tid & 63;          // column pair (cols 2cp, 2cp+1)
        const int fh  = (tid >> 6) & 1;    // 64-row half
        const int sub = tid >> 7;          // 0..3
        float* colp = Ssh + (fh * 64) * SSTR + 2 * cp;

        // Y pass: sub owns i-groups {2sub, 2sub+1}; in-place safe per group.
        #pragma unroll
        for (int g = 0; g < 2; g++) {
            int i = sub * 2 + g;
            u64 v[8];
            #pragma unroll
            for (int j = 0; j < 8; j++)
                v[j] = *reinterpret_cast<const u64*>(colp + (i * 8 + j) * SSTR);
            #pragma unroll
            for (int l = 0; l < 8; l++) {
                u64 acc = fmul2(UyB[l * 8], v[0]);
                #pragma unroll
                for (int j = 1; j < 8; j++) acc = ffma2(UyB[l * 8 + j], v[j], acc);
                *reinterpret_cast<u64*>(colp + (i * 8 + l) * SSTR) = acc;
            }
        }
        __syncthreads();

        // X pass: sub owns l in {2sub, 2sub+1}; preload t before writes.
        #pragma unroll
        for (int li = 0; li < 2; li++) {
            int l = sub * 2 + li;
            u64 t[8];
            #pragma unroll
            for (int i = 0; i < 8; i++)
                t[i] = *reinterpret_cast<const u64*>(colp + (i * 8 + l) * SSTR);
            #pragma unroll
            for (int k = 0; k < 8; k++) {
                u64 acc = fmul2(UxB[k * 8], t[0]);
                #pragma unroll
                for (int i = 1; i < 8; i++) acc = ffma2(UxB[k * 8 + i], t[i], acc);
                *reinterpret_cast<u64*>(colp + (k * 8 + l) * SSTR) = acc;
            }
        }
    }
    __syncthreads();

    // ---------- Stage 2: right transform per ROW, in place, f32x2 ----------
    {
        const int lane = tid & 127;        // row
        const int fh   = (tid >> 7) & 1;   // 64-col half
        const int sub  = tid >> 8;         // 0..1
        float* rowp = Ssh + lane * SSTR + fh * 64;

        // Y pass: sub owns i-groups sub*4..+3; vectorized over l-pairs via UyT.
        #pragma unroll
        for (int gi = 0; gi < 4; gi++) {
            int i = sub * 4 + gi;
            float4 va = *reinterpret_cast<const float4*>(rowp + i * 8);
            float4 vb = *reinterpret_cast<const float4*>(rowp + i * 8 + 4);
            u64 bv[8] = {bc2(va.x), bc2(va.y), bc2(va.z), bc2(va.w),
                         bc2(vb.x), bc2(vb.y), bc2(vb.z), bc2(vb.w)};
            u64 a2[4];
            #pragma unroll
            for (int l2 = 0; l2 < 4; l2++) {
                u64 acc = fmul2(UyT[l2], bv[0]);
                #pragma unroll
                for (int j = 1; j < 8; j++) acc = ffma2(UyT[j * 4 + l2], bv[j], acc);
                a2[l2] = acc;
            }
            ulonglong2 s0; s0.x = a2[0]; s0.y = a2[1];
            ulonglong2 s1; s1.x = a2[2]; s1.y = a2[3];
            *reinterpret_cast<ulonglong2*>(rowp + i * 8)     = s0;
            *reinterpret_cast<ulonglong2*>(rowp + i * 8 + 4) = s1;
        }
        __syncthreads();

        // X pass: sub owns the l-quad at offset 4*sub; LDS.128 (conflict-free),
        // two f32x2 accumulators per k, preload before in-place writes.
        {
            ulonglong2 t2[8];
            #pragma unroll
            for (int i = 0; i < 8; i++)
                t2[i] = *reinterpret_cast<const ulonglong2*>(rowp + i * 8 + 4 * sub);
            #pragma unroll
            for (int k = 0; k < 8; k++) {
                u64 acc0 = fmul2(UxB[k * 8], t2[0].x);
                u64 acc1 = fmul2(UxB[k * 8], t2[0].y);
                #pragma unroll
                for (int i = 1; i < 8; i++) {
                    u64 u = UxB[k * 8 + i];
                    acc0 = ffma2(u, t2[i].x, acc0);
                    acc1 = ffma2(u, t2[i].y, acc1);
                }
                ulonglong2 o; o.x = acc0; o.y = acc1;
                *reinterpret_cast<ulonglong2*>(rowp + k * 8 + 4 * sub) = o;
            }
        }
    }
    __syncthreads();

    // ---------- Combine: each M2 float4 read once, fan out to 16 blocks, f32x2 ----------
    {
        u64 cg[8];
        #pragma unroll
        for (int q = 0; q < 8; q++) cg[q] = UcB[q];

        float* __restrict__ Y = out_g + (size_t)b * 65536;

        #pragma unroll
        for (int it = 0; it < 2; it++) {
            int idx = tid + it * 512;          // 1024 (kl, s4) positions
            int s4  = idx & 15;
            int kl  = idx >> 4;

            const float* p0 = Ssh + kl * SSTR + s4 * 4;          // f = 0 row
            const float* p1 = Ssh + (64 + kl) * SSTR + s4 * 4;   // f = 1 row
            ulonglong2 x00 = *reinterpret_cast<const ulonglong2*>(p0);
            ulonglong2 x01 = *reinterpret_cast<const ulonglong2*>(p0 + 64);
            ulonglong2 x10 = *reinterpret_cast<const ulonglong2*>(p1);
            ulonglong2 x11 = *reinterpret_cast<const ulonglong2*>(p1 + 64);

            #pragma unroll
            for (int g = 0; g < 4; g++) {
                u64 g0 = cg[g * 2], g1 = cg[g * 2 + 1];
                u64 e0a = ffma2(g1, x10.x, fmul2(g0, x00.x));
                u64 e0b = ffma2(g1, x10.y, fmul2(g0, x00.y));
                u64 e1a = ffma2(g1, x11.x, fmul2(g0, x01.x));
                u64 e1b = ffma2(g1, x11.y, fmul2(g0, x01.y));
                #pragma unroll
                for (int gp = 0; gp < 4; gp++) {
                    u64 d0 = cg[gp * 2], d1 = cg[gp * 2 + 1];
                    ulonglong2 o;
                    o.x = ffma2(d1, e1a, fmul2(d0, e0a));
                    o.y = ffma2(d1, e1b, fmul2(d0, e0b));
                    *reinterpret_cast<ulonglong2*>(
                        Y + (size_t)(g * 64 + kl) * 256 + gp * 64 + s4 * 4) = o;
                }
            }
        }
    }
}

extern "C" void kernel_launch(void* const* d_in, const int* in_sizes, int n_in,
                              void* d_out, int out_size)
{
    const float* rho = (const float*)d_in[0];
    const float* ux  = (const float*)d_in[1];
    const float* uy  = (const float*)d_in[2];
    const float* uc  = (const float*)d_in[3];
    float* out = (float*)d_out;

    const int nb = in_sizes[0] / (128 * 128);   // 256 batches

    cudaFuncSetAttribute(qconv_kernel,
                         cudaFuncAttributeMaxDynamicSharedMemorySize, SMEM_BYTES);
    qconv_kernel<<<nb, 512, SMEM_BYTES>>>(rho, ux, uy, uc, out);
}